// round 15
// baseline (speedup 1.0000x reference)
#include <cuda_runtime.h>
#include <cuda_bf16.h>
#include <cstdint>

// Problem constants (fixed shapes per reference)
#define Bn   8
#define Nn   1024
#define Fin  128
#define Cc   128
#define Ef   64
#define Hh   4
#define NEG  0.2f
#define ROWS (Bn * 1024)        // 8192
#define ICHUNK 16               // i-rows per block in main kernel
#define NBKT   256              // (64 i-chunks) x (4 j-tiles)
#define BCAP   1024             // bucket capacity (mean occupancy ~128)

// Scratch (device globals — no allocation allowed).
// g_bcnt/g_bread start BSS-zero; main kernel ticket-resets them each run
// (R13-validated), so every launch sequence starts from zeroed counters.
__device__ float          g_M[Fin * 12];    // cols 0-3: As, 4-7: Ad, 8-11: Ae
// Unified exp tables: 0=exp(s) 1=exp(.2s) 2=exp(d) 3=exp(.2d)
//                     4=exp(s+p) 5=exp(.2(s+p)) 6=exp(d-p) 7=exp(.2(d-p))
__device__ float4         g_T[8][ROWS];
__device__ int            g_bcnt [NBKT];    // per-tile edge counts
__device__ int            g_bread[NBKT];    // consumer tickets (self-reset)
__device__ unsigned short g_bdata[NBKT * BCAP];  // packed cells: i_loc<<8 | j_loc

// ---------------------------------------------------------------------------
// Kernel 1: fold weights (warp-per-entry, 1536 warps = 192 blocks; validated
// R12) + bucket edges by output tile (grid-stride; counters are zero from
// BSS / previous run's ticket reset).
// ---------------------------------------------------------------------------
__global__ __launch_bounds__(256) void m_bucket_kernel(
        const int*   __restrict__ edge_index, int E,
        const float* __restrict__ W_lin,
        const float* __restrict__ a_src,
        const float* __restrict__ a_dst,
        const float* __restrict__ W_edge,
        const float* __restrict__ a_edge) {
    const int t = blockIdx.x * blockDim.x + threadIdx.x;

    // ---- bucket fill
    {
        const int nt = gridDim.x * blockDim.x;
        for (int e = t; e < E; e += nt) {
            const int i = edge_index[e];
            const int j = edge_index[E + e];
            const int bkt = (i >> 4) * 4 + (j >> 8);
            const int pos = atomicAdd(&g_bcnt[bkt], 1);
            if (pos < BCAP)
                g_bdata[bkt * BCAP + pos] =
                    (unsigned short)(((i & 15) << 8) | (j & 255));
        }
    }

    // ---- M entries: warp gw computes M[f, col]
    const int gw   = t >> 5;      // 0..1535
    const int lane = t & 31;
    const int f   = gw / 12;      // 0..127
    const int col = gw % 12;
    float acc = 0.0f;
    if (col < 8) {
        const float* __restrict__ av = (col < 4) ? a_src : a_dst;
        const int h = col & 3;
        #pragma unroll
        for (int k = 0; k < 4; k++) {
            const int c = lane + k * 32;
            acc += W_lin[f * Cc + c] * av[c * Hh + h];
        }
    } else {
        const int h = col - 8;
        #pragma unroll
        for (int k = 0; k < 2; k++) {
            const int d = lane + k * 32;
            acc += W_edge[f * Ef + d] * a_edge[d * Hh + h];
        }
    }
    #pragma unroll
    for (int o = 16; o > 0; o >>= 1) acc += __shfl_xor_sync(0xffffffffu, acc, o);
    if (lane == 0) g_M[f * 12 + col] = acc;
}

// ---------------------------------------------------------------------------
// Kernel 2: PURE rows. Warp per row; after the xor-butterfly every lane
// holds all 12 sums, so each of the 32 lanes computes exactly ONE __expf
// and one scalar store into g_T (parallel MUFU instead of 32 serial on
// lane 0).  Table t = lane>>2, component h = lane&3.
// ---------------------------------------------------------------------------
__global__ __launch_bounds__(256) void rows_kernel(const float* __restrict__ src) {
    __shared__ float sM[Fin * 12];
    for (int idx = threadIdx.x; idx < Fin * 12; idx += 256) sM[idx] = g_M[idx];
    __syncthreads();

    const int gwarp  = (blockIdx.x * blockDim.x + threadIdx.x) >> 5;
    const int lane   = threadIdx.x & 31;
    const int nwarps = (gridDim.x * blockDim.x) >> 5;

    const int tbl = lane >> 2;     // 0..7
    const int h   = lane & 3;      // 0..3
    float* __restrict__ Tf = reinterpret_cast<float*>(g_T);

    for (int r = gwarp; r < ROWS; r += nwarps) {
        const float4 sv = reinterpret_cast<const float4*>(src + (size_t)r * Fin)[lane];
        float acc[12];
        #pragma unroll
        for (int q = 0; q < 12; q++) acc[q] = 0.0f;

        const float vals[4] = {sv.x, sv.y, sv.z, sv.w};
        #pragma unroll
        for (int k = 0; k < 4; k++) {
            const int f = lane * 4 + k;
            const float x = vals[k];
            #pragma unroll
            for (int q = 0; q < 12; q++) acc[q] += x * sM[f * 12 + q];
        }
        #pragma unroll
        for (int o = 16; o > 0; o >>= 1) {
            #pragma unroll
            for (int q = 0; q < 12; q++)
                acc[q] += __shfl_xor_sync(0xffffffffu, acc[q], o);
        }
        // every lane now has the full s(0-3), d(4-7), p(8-11)
        const float a0 = acc[h], a4 = acc[4 + h], a8 = acc[8 + h];
        const int g = tbl >> 1;    // 0: s, 1: d, 2: s+p, 3: d-p
        float base = (g == 0) ? a0 : (g == 1) ? a4
                   : (g == 2) ? (a0 + a8) : (a4 - a8);
        const float arg = (tbl & 1) ? NEG * base : base;
        Tf[((size_t)tbl * ROWS + r) * 4 + h] = __expf(arg);
    }
}

// ---------------------------------------------------------------------------
// Kernel 3: fused MAIN. Block = (j-tile, i-chunk, b). Builds the 4 KB smem
// multiplicity tile, once-per-warp imask (validated R14), then streams
// 16x256 quads. Edge math is pure register algebra:
//   c==1: e = fmax(u*w, u2*w2)
//   c>=2: e = fmax((u*w)*r^(c-1), (u2*w2)*r2^(c-1)),  r = u*w/(es*ed)
// No g_S/g_D/g_P loads — fewer regs, higher occupancy. Ticket reset
// (R13-validated) re-zeroes bucket counters for the next run.
// ---------------------------------------------------------------------------
__global__ __launch_bounds__(256) void attn_main_kernel(float4* __restrict__ out) {
    __shared__ unsigned scnt[1024];            // uint8[16][256] packed

    const int jt = blockIdx.x;                 // 0..3
    const int ic = blockIdx.y;                 // 0..63
    const int b  = blockIdx.z;
    const int j  = jt * 256 + threadIdx.x;
    const int i0 = ic * ICHUNK;
    const int rj = b * Nn + j;
    const int bkt = ic * 4 + jt;

    // build smem cnt from this tile's bucket
    #pragma unroll
    for (int k = 0; k < 4; k++) scnt[threadIdx.x + k * 256] = 0u;
    __syncthreads();
    {
        const int n = g_bcnt[bkt] < BCAP ? g_bcnt[bkt] : BCAP;
        for (int k = threadIdx.x; k < n; k += 256) {
            const unsigned cell = g_bdata[bkt * BCAP + k];   // i_loc<<8 | j_loc
            atomicAdd(&scnt[cell >> 2], 1u << ((cell & 3) * 8));
        }
    }
    __syncthreads();

    // ticket: last of the Bn consumers resets the bucket counters
    if (threadIdx.x == 0) {
        const int tk = atomicAdd(&g_bread[bkt], 1);
        if (tk == Bn - 1) { g_bcnt[bkt] = 0; g_bread[bkt] = 0; }
    }

    const unsigned char* sc8 = reinterpret_cast<const unsigned char*>(scnt);

    // once-per-warp 16-bit mask of i-iters containing any edge in this
    // warp's 32-j window (one ballot; validated R14)
    const int wid  = threadIdx.x >> 5;
    const int lane = threadIdx.x & 31;
    unsigned pred = 0u;
    if (lane < ICHUNK) {
        const unsigned* wptr = &scnt[(lane << 6) + (wid << 3)];
        unsigned a = 0u;
        #pragma unroll
        for (int k = 0; k < 8; k++) a |= wptr[k];
        pred = a;
    }
    const unsigned imask = __ballot_sync(0xffffffffu, pred != 0u);

    // j-side tables in registers
    const float4 ed  = __ldg(&g_T[2][rj]);
    const float4 ed2 = __ldg(&g_T[3][rj]);
    const float4 w   = __ldg(&g_T[6][rj]);
    const float4 w2  = __ldg(&g_T[7][rj]);

    const float4* __restrict__ esrow  = g_T[0] + b * Nn + i0;
    const float4* __restrict__ es2row = g_T[1] + b * Nn + i0;
    const float4* __restrict__ urow   = g_T[4] + b * Nn + i0;
    const float4* __restrict__ u2row  = g_T[5] + b * Nn + i0;
    float4* __restrict__ optr = out + ((size_t)(b * Nn + i0)) * Nn + j;

    #pragma unroll
    for (int i = 0; i < ICHUNK; i++) {
        const float4 es  = __ldg(esrow  + i);   // broadcast across warp
        const float4 es2 = __ldg(es2row + i);

        float4 e;
        e.x = fmaxf(es.x * ed.x, es2.x * ed2.x);
        e.y = fmaxf(es.y * ed.y, es2.y * ed2.y);
        e.z = fmaxf(es.z * ed.z, es2.z * ed2.z);
        e.w = fmaxf(es.w * ed.w, es2.w * ed2.w);

        if (imask & (1u << i)) {   // warp-uniform (~63% of iters)
            const unsigned c = sc8[i * 256 + threadIdx.x];
            const float4 u  = __ldg(urow  + i);
            const float4 u2 = __ldg(u2row + i);
            if (c != 0u) {
                float p0 = u.x * w.x,   p1 = u.y * w.y;
                float p2 = u.z * w.z,   p3 = u.w * w.w;
                float n0 = u2.x * w2.x, n1 = u2.y * w2.y;
                float n2 = u2.z * w2.z, n3 = u2.w * w2.w;
                if (c > 1u) {          // duplicate edges: ~500 cells total
                    const float r0 = __fdividef(p0, es.x * ed.x);
                    const float r1 = __fdividef(p1, es.y * ed.y);
                    const float r2 = __fdividef(p2, es.z * ed.z);
                    const float r3 = __fdividef(p3, es.w * ed.w);
                    const float q0 = __fdividef(n0, es2.x * ed2.x);
                    const float q1 = __fdividef(n1, es2.y * ed2.y);
                    const float q2 = __fdividef(n2, es2.z * ed2.z);
                    const float q3 = __fdividef(n3, es2.w * ed2.w);
                    for (unsigned k = 1; k < c; k++) {
                        p0 *= r0; p1 *= r1; p2 *= r2; p3 *= r3;
                        n0 *= q0; n1 *= q1; n2 *= q2; n3 *= q3;
                    }
                }
                e.x = fmaxf(p0, n0); e.y = fmaxf(p1, n1);
                e.z = fmaxf(p2, n2); e.w = fmaxf(p3, n3);
            }
        }

        const float inv = __fdividef(1.0f, (e.x + e.y) + (e.z + e.w));
        __stcs(optr + (size_t)i * Nn,
               make_float4(e.x * inv, e.y * inv, e.z * inv, e.w * inv));
    }
}

// ---------------------------------------------------------------------------
// Launch
// Inputs (metadata order): src, edge_index, W_lin, a_src, a_dst, W_edge, a_edge
// ---------------------------------------------------------------------------
extern "C" void kernel_launch(void* const* d_in, const int* in_sizes, int n_in,
                              void* d_out, int out_size) {
    const float* src        = (const float*)d_in[0];
    const int*   edge_index = (const int*)  d_in[1];
    const float* W_lin      = (const float*)d_in[2];
    const float* a_src      = (const float*)d_in[3];
    const float* a_dst      = (const float*)d_in[4];
    const float* W_edge     = (const float*)d_in[5];
    const float* a_edge     = (const float*)d_in[6];
    const int E = in_sizes[1] / 2;

    m_bucket_kernel<<<192, 256>>>(edge_index, E,
                                  W_lin, a_src, a_dst, W_edge, a_edge);
    rows_kernel<<<256, 256>>>(src);
    attn_main_kernel<<<dim3(Nn / 256, Nn / ICHUNK, Bn), 256>>>((float4*)d_out);
}

// round 17
// speedup vs baseline: 1.0523x; 1.0523x over previous
#include <cuda_runtime.h>
#include <cuda_bf16.h>
#include <cstdint>

// Problem constants (fixed shapes per reference)
#define Bn   8
#define Nn   1024
#define Fin  128
#define Cc   128
#define Ef   64
#define Hh   4
#define NEG  0.2f
#define ROWS (Bn * 1024)        // 8192
#define ICHUNK 32               // i-rows per block in main kernel
#define NBKT   128              // (32 i-chunks) x (4 j-tiles)
#define BCAP   1024             // bucket capacity (mean occupancy ~256)

// Scratch (device globals — no allocation allowed).
// g_bcnt/g_bread start BSS-zero; main kernel ticket-resets them each run
// (R13/R15-validated), so every launch sequence starts from zeroed counters.
__device__ float          g_M[Fin * 12];    // cols 0-3: As, 4-7: Ad, 8-11: Ae
// Unified exp tables: 0=exp(s) 1=exp(.2s) 2=exp(d) 3=exp(.2d)
//                     4=exp(s+p) 5=exp(.2(s+p)) 6=exp(d-p) 7=exp(.2(d-p))
__device__ float4         g_T[8][ROWS];
__device__ int            g_bcnt [NBKT];    // per-tile edge counts
__device__ int            g_bread[NBKT];    // consumer tickets (self-reset)
__device__ unsigned short g_bdata[NBKT * BCAP];  // packed cells: i_loc<<8 | j_loc

// ---------------------------------------------------------------------------
// Kernel 1: fold weights ONLY — warp-per-entry, 1536 warps = 192 blocks
// (R12-validated, runs at the small-kernel floor).
// ---------------------------------------------------------------------------
__global__ __launch_bounds__(256) void m_zero_kernel(
        const float* __restrict__ W_lin,
        const float* __restrict__ a_src,
        const float* __restrict__ a_dst,
        const float* __restrict__ W_edge,
        const float* __restrict__ a_edge) {
    const int t = blockIdx.x * blockDim.x + threadIdx.x;
    const int gw   = t >> 5;      // 0..1535
    const int lane = t & 31;
    const int f   = gw / 12;      // 0..127
    const int col = gw % 12;
    float acc = 0.0f;
    if (col < 8) {
        const float* __restrict__ av = (col < 4) ? a_src : a_dst;
        const int h = col & 3;
        #pragma unroll
        for (int k = 0; k < 4; k++) {
            const int c = lane + k * 32;
            acc += W_lin[f * Cc + c] * av[c * Hh + h];
        }
    } else {
        const int h = col - 8;
        #pragma unroll
        for (int k = 0; k < 2; k++) {
            const int d = lane + k * 32;
            acc += W_edge[f * Ef + d] * a_edge[d * Hh + h];
        }
    }
    #pragma unroll
    for (int o = 16; o > 0; o >>= 1) acc += __shfl_xor_sync(0xffffffffu, acc, o);
    if (lane == 0) g_M[f * 12 + col] = acc;
}

// ---------------------------------------------------------------------------
// Kernel 2: bucket fill (atomics hidden under the FMA-heavy rows phase —
// R14 placement) + warp-per-row projections with lane-parallel exp (R15):
// after the butterfly every lane holds all 12 sums; lane = 4*tbl+h computes
// exactly one __expf and one scalar store into g_T.
// ---------------------------------------------------------------------------
__global__ __launch_bounds__(256) void rows_bucket_kernel(
        const float* __restrict__ src,
        const int*   __restrict__ edge_index, int E) {
    // ---- bucket fill: tile = (i>>5, j>>8); counters zero from prior reset
    {
        const int t  = blockIdx.x * blockDim.x + threadIdx.x;
        const int nt = gridDim.x * blockDim.x;
        for (int e = t; e < E; e += nt) {
            const int i = edge_index[e];
            const int j = edge_index[E + e];
            const int bkt = (i >> 5) * 4 + (j >> 8);
            const int pos = atomicAdd(&g_bcnt[bkt], 1);
            if (pos < BCAP)
                g_bdata[bkt * BCAP + pos] =
                    (unsigned short)(((i & 31) << 8) | (j & 255));
        }
    }

    // ---- rows
    __shared__ float sM[Fin * 12];
    for (int idx = threadIdx.x; idx < Fin * 12; idx += 256) sM[idx] = g_M[idx];
    __syncthreads();

    const int gwarp  = (blockIdx.x * blockDim.x + threadIdx.x) >> 5;
    const int lane   = threadIdx.x & 31;
    const int nwarps = (gridDim.x * blockDim.x) >> 5;

    const int tbl = lane >> 2;     // 0..7
    const int h   = lane & 3;      // 0..3
    float* __restrict__ Tf = reinterpret_cast<float*>(g_T);

    for (int r = gwarp; r < ROWS; r += nwarps) {
        const float4 sv = reinterpret_cast<const float4*>(src + (size_t)r * Fin)[lane];
        float acc[12];
        #pragma unroll
        for (int q = 0; q < 12; q++) acc[q] = 0.0f;

        const float vals[4] = {sv.x, sv.y, sv.z, sv.w};
        #pragma unroll
        for (int k = 0; k < 4; k++) {
            const int f = lane * 4 + k;
            const float x = vals[k];
            #pragma unroll
            for (int q = 0; q < 12; q++) acc[q] += x * sM[f * 12 + q];
        }
        #pragma unroll
        for (int o = 16; o > 0; o >>= 1) {
            #pragma unroll
            for (int q = 0; q < 12; q++)
                acc[q] += __shfl_xor_sync(0xffffffffu, acc[q], o);
        }
        // every lane holds full s(0-3), d(4-7), p(8-11)
        const float a0 = acc[h], a4 = acc[4 + h], a8 = acc[8 + h];
        const int g = tbl >> 1;    // 0: s, 1: d, 2: s+p, 3: d-p
        const float base = (g == 0) ? a0 : (g == 1) ? a4
                         : (g == 2) ? (a0 + a8) : (a4 - a8);
        const float arg = (tbl & 1) ? NEG * base : base;
        Tf[((size_t)tbl * ROWS + r) * 4 + h] = __expf(arg);
    }
}

// ---------------------------------------------------------------------------
// Kernel 3: fused MAIN. Block = (j-tile, i-chunk, b) = 1024 blocks of
// 256 threads x 32 i-iters. Builds an 8 KB smem multiplicity tile from its
// bucket, computes a 32-bit per-warp imask (lane i ORs row i; one ballot),
// then streams quads. Edge math is pure register algebra (R15-validated):
//   c==1: e = fmax(u*w, u2*w2)
//   c>=2: e = fmax((u*w)*r^(c-1), ...),  r = u*w/(es*ed)   — no extra loads
// Ticket reset re-zeroes bucket counters for the next run.
// ---------------------------------------------------------------------------
__global__ __launch_bounds__(256) void attn_main_kernel(float4* __restrict__ out) {
    __shared__ unsigned scnt[ICHUNK * 64];     // uint8[32][256] packed = 8 KB

    const int jt = blockIdx.x;                 // 0..3
    const int ic = blockIdx.y;                 // 0..31
    const int b  = blockIdx.z;
    const int j  = jt * 256 + threadIdx.x;
    const int i0 = ic * ICHUNK;
    const int rj = b * Nn + j;
    const int bkt = ic * 4 + jt;

    // build smem cnt from this tile's bucket
    #pragma unroll
    for (int k = 0; k < 8; k++) scnt[threadIdx.x + k * 256] = 0u;
    __syncthreads();
    {
        const int n = g_bcnt[bkt] < BCAP ? g_bcnt[bkt] : BCAP;
        for (int k = threadIdx.x; k < n; k += 256) {
            const unsigned cell = g_bdata[bkt * BCAP + k];   // i_loc<<8 | j_loc
            atomicAdd(&scnt[cell >> 2], 1u << ((cell & 3) * 8));
        }
    }
    __syncthreads();

    // ticket: last of the Bn consumers resets the bucket counters
    if (threadIdx.x == 0) {
        const int tk = atomicAdd(&g_bread[bkt], 1);
        if (tk == Bn - 1) { g_bcnt[bkt] = 0; g_bread[bkt] = 0; }
    }

    const unsigned char* sc8 = reinterpret_cast<const unsigned char*>(scnt);

    // per-warp 32-bit mask: lane i ORs row i's 8 words in this warp's window
    const int wid  = threadIdx.x >> 5;
    const int lane = threadIdx.x & 31;
    unsigned pred;
    {
        const unsigned* wptr = &scnt[(lane << 6) + (wid << 3)];  // row*64+wid*8
        unsigned a = 0u;
        #pragma unroll
        for (int k = 0; k < 8; k++) a |= wptr[k];
        pred = a;
    }
    const unsigned imask = __ballot_sync(0xffffffffu, pred != 0u);

    // j-side tables in registers
    const float4 ed  = __ldg(&g_T[2][rj]);
    const float4 ed2 = __ldg(&g_T[3][rj]);
    const float4 w   = __ldg(&g_T[6][rj]);
    const float4 w2  = __ldg(&g_T[7][rj]);

    const float4* __restrict__ esrow  = g_T[0] + b * Nn + i0;
    const float4* __restrict__ es2row = g_T[1] + b * Nn + i0;
    const float4* __restrict__ urow   = g_T[4] + b * Nn + i0;
    const float4* __restrict__ u2row  = g_T[5] + b * Nn + i0;
    float4* __restrict__ optr = out + ((size_t)(b * Nn + i0)) * Nn + j;

    #pragma unroll 4
    for (int i = 0; i < ICHUNK; i++) {
        const float4 es  = __ldg(esrow  + i);   // broadcast across warp
        const float4 es2 = __ldg(es2row + i);

        float4 e;
        e.x = fmaxf(es.x * ed.x, es2.x * ed2.x);
        e.y = fmaxf(es.y * ed.y, es2.y * ed2.y);
        e.z = fmaxf(es.z * ed.z, es2.z * ed2.z);
        e.w = fmaxf(es.w * ed.w, es2.w * ed2.w);

        if (imask & (1u << i)) {   // warp-uniform (~63% of iters)
            const unsigned c = sc8[i * 256 + threadIdx.x];
            const float4 u  = __ldg(urow  + i);
            const float4 u2 = __ldg(u2row + i);
            if (c != 0u) {
                float p0 = u.x * w.x,   p1 = u.y * w.y;
                float p2 = u.z * w.z,   p3 = u.w * w.w;
                float n0 = u2.x * w2.x, n1 = u2.y * w2.y;
                float n2 = u2.z * w2.z, n3 = u2.w * w2.w;
                if (c > 1u) {          // duplicate edges: ~500 cells total
                    const float r0 = __fdividef(p0, es.x * ed.x);
                    const float r1 = __fdividef(p1, es.y * ed.y);
                    const float r2 = __fdividef(p2, es.z * ed.z);
                    const float r3 = __fdividef(p3, es.w * ed.w);
                    const float q0 = __fdividef(n0, es2.x * ed2.x);
                    const float q1 = __fdividef(n1, es2.y * ed2.y);
                    const float q2 = __fdividef(n2, es2.z * ed2.z);
                    const float q3 = __fdividef(n3, es2.w * ed2.w);
                    for (unsigned k = 1; k < c; k++) {
                        p0 *= r0; p1 *= r1; p2 *= r2; p3 *= r3;
                        n0 *= q0; n1 *= q1; n2 *= q2; n3 *= q3;
                    }
                }
                e.x = fmaxf(p0, n0); e.y = fmaxf(p1, n1);
                e.z = fmaxf(p2, n2); e.w = fmaxf(p3, n3);
            }
        }

        const float inv = __fdividef(1.0f, (e.x + e.y) + (e.z + e.w));
        __stcs(optr + (size_t)i * Nn,
               make_float4(e.x * inv, e.y * inv, e.z * inv, e.w * inv));
    }
}

// ---------------------------------------------------------------------------
// Launch
// Inputs (metadata order): src, edge_index, W_lin, a_src, a_dst, W_edge, a_edge
// ---------------------------------------------------------------------------
extern "C" void kernel_launch(void* const* d_in, const int* in_sizes, int n_in,
                              void* d_out, int out_size) {
    const float* src        = (const float*)d_in[0];
    const int*   edge_index = (const int*)  d_in[1];
    const float* W_lin      = (const float*)d_in[2];
    const float* a_src      = (const float*)d_in[3];
    const float* a_dst      = (const float*)d_in[4];
    const float* W_edge     = (const float*)d_in[5];
    const float* a_edge     = (const float*)d_in[6];
    const int E = in_sizes[1] / 2;

    m_zero_kernel<<<192, 256>>>(W_lin, a_src, a_dst, W_edge, a_edge);
    rows_bucket_kernel<<<256, 256>>>(src, edge_index, E);
    attn_main_kernel<<<dim3(Nn / 256, Nn / ICHUNK, Bn), 256>>>((float4*)d_out);
}